// round 12
// baseline (speedup 1.0000x reference)
#include <cuda_runtime.h>

// NeRF fine sampling + merge. TWO rays per warp (16 lanes x 8 elements each).
// R11 + bank-conflict padding on all randomly-indexed smem tables.
#define SC   64
#define SF   128
#define NOUT 192
#define WPB  8
#define FULL 0xffffffffu

// per-(warp,half) blob layout (float offsets)
#define TA_OFF    0     // float4[18]: ta[g] at slot g+(g>>3)
#define DP_OFF    72    // float2[70]: dpair[i] at slot i+2*(i>>4)
#define CDF_OFF   212   // float[72]:  cdf[i] at slot i+4*(i>>5)
#define PREF_OFF  284   // int[64]
#define BLOB_SZ   360   // 360 mod 32 = 8 -> halves de-aliased in banks
#define OBF_SZ    216   // obf[p] at slot p+4*(p>>5), p<=191 -> slot<=211

__device__ __forceinline__ void ce(float& x, float& y, bool asc) {
    float lo = fminf(x, y), hi = fmaxf(x, y);
    x = asc ? lo : hi;
    y = asc ? hi : lo;
}
__device__ __forceinline__ int OSL(int p) { return p + 4 * (p >> 5); }

__global__ __launch_bounds__(32 * WPB, 5)
void fine_sample_kernel(const float* __restrict__ dists,
                        const float* __restrict__ weights,
                        const float* __restrict__ rands,
                        float* __restrict__ out, int B)
{
    __shared__ __align__(16) float blob_s[WPB][2][BLOB_SZ];
    __shared__ __align__(16) float out_s[WPB][2][OBF_SZ];

    const int wid  = threadIdx.x >> 5;
    const int lane = threadIdx.x & 31;
    const int half = lane >> 4;
    const int hl   = lane & 15;
    const int ray  = (blockIdx.x * WPB + wid) * 2 + half;

    float* blob = blob_s[wid][half];
    float4* ta    = (float4*)(blob + TA_OFF);
    float2* dpair = (float2*)(blob + DP_OFF);
    float*  cdfs  = blob + CDF_OFF;
    int*    pref  = (int*)(blob + PREF_OFF);

    // pref default: 128
    ((int4*)pref)[hl] = make_int4(128, 128, 128, 128);

    const int wi = 4 * hl;
    // ---- loads ----
    const float4* dptr4 = (const float4*)(dists + (size_t)ray * SC);
    float4 dd = dptr4[hl];                               // d[4hl..4hl+3] (kept live)
    {
        const float* wptr = weights + (size_t)ray * (SC - 1);
        float w0 = wptr[wi]     + 0.01f;
        float w1 = wptr[wi + 1] + 0.01f;
        float w2 = wptr[wi + 2] + 0.01f;
        float w3 = (hl < 15) ? (wptr[wi + 3] + 0.01f) : 0.0f;

        // ---- scan (width 16, both rays in parallel) ----
        float p1 = w0, p2 = p1 + w1, p3 = p2 + w2;
        float e  = p3 + w3;
        float E = e;
        #pragma unroll
        for (int off = 1; off < 16; off <<= 1) {
            float t = __shfl_up_sync(FULL, E, off);
            if (hl >= off) E += t;
        }
        float total = __shfl_sync(FULL, E, lane | 15);
        float inv = 1.0f / total;
        float c0e = E - e;
        float4 cv = make_float4(c0e * inv, (c0e + p1) * inv,
                                (c0e + p2) * inv, (c0e + p3) * inv);
        float ctop = E * inv;                            // cdf[4hl+4]; hl=15 -> 1.0
        // cdf store: slot 4hl + 4*(hl>>3), float4-aligned
        *((float4*)(cdfs + wi + 4 * (hl >> 3))) = cv;
        ta[hl + (hl >> 3)] = make_float4(cv.y, cv.z, cv.w, ctop);

        // ---- dpair table: (d[i], d[i+1]) at padded slots ----
        float dnext = __shfl_down_sync(FULL, dd.x, 1);
        if (hl == 15) dnext = dd.w;                      // d[64] := d[63]
        float2* dpw = dpair + wi + 2 * (hl >> 2);        // slot wi + 2*(wi>>4)
        ((float4*)dpw)[0] = make_float4(dd.x, dd.y, dd.y, dd.z);
        ((float4*)dpw)[1] = make_float4(dd.z, dd.w, dd.w, dnext);
    }

    // ---- load 8 u's (element index i = hl*8 + m) ----
    float k[8];
    {
        const float4* up4 = (const float4*)(rands + (size_t)ray * SF);
        float4 ua = up4[2 * hl], ub = up4[2 * hl + 1];
        k[0]=ua.x; k[1]=ua.y; k[2]=ua.z; k[3]=ua.w;
        k[4]=ub.x; k[5]=ub.y; k[6]=ub.z; k[7]=ub.w;
    }

    // ---- bitonic sort of 128 u's across 16 lanes x 8 regs ----
    ce(k[0], k[1], true);  ce(k[2], k[3], false);
    ce(k[4], k[5], true);  ce(k[6], k[7], false);
    ce(k[0], k[2], true);  ce(k[1], k[3], true);
    ce(k[0], k[1], true);  ce(k[2], k[3], true);
    ce(k[4], k[6], false); ce(k[5], k[7], false);
    ce(k[4], k[5], false); ce(k[6], k[7], false);
    {
        bool a = (hl & 1) == 0;
        ce(k[0], k[4], a); ce(k[1], k[5], a); ce(k[2], k[6], a); ce(k[3], k[7], a);
        ce(k[0], k[2], a); ce(k[1], k[3], a); ce(k[4], k[6], a); ce(k[5], k[7], a);
        ce(k[0], k[1], a); ce(k[2], k[3], a); ce(k[4], k[5], a); ce(k[6], k[7], a);
    }
    #pragma unroll
    for (int kk = 16; kk <= 128; kk <<= 1) {
        bool a = (hl & (kk >> 3)) == 0;
        #pragma unroll
        for (int L = kk >> 4; L >= 1; L >>= 1) {
            bool dm = (((hl & L) == 0) == a);
            #pragma unroll
            for (int m = 0; m < 8; m++) {
                float p = __shfl_xor_sync(FULL, k[m], L);
                k[m] = dm ? fminf(k[m], p) : fmaxf(k[m], p);
            }
        }
        ce(k[0], k[4], a); ce(k[1], k[5], a); ce(k[2], k[6], a); ce(k[3], k[7], a);
        ce(k[0], k[2], a); ce(k[1], k[3], a); ce(k[4], k[6], a); ce(k[5], k[7], a);
        ce(k[0], k[1], a); ce(k[2], k[3], a); ce(k[4], k[5], a); ce(k[6], k[7], a);
    }
    __syncwarp();   // tables ready

    // ---- reload probes (broadcast LDS at padded slots) ----
    float c8  = cdfs[8],  c16 = cdfs[16], c24 = cdfs[24], c32 = cdfs[36];
    float c40 = cdfs[44], c48 = cdfs[52], c56 = cdfs[60];

    float* obf = out_s[wid][half];

    // ---- search + interp on SORTED u's; scatter; first-occurrence ----
    int prev = -1, idx0 = 0;
    #pragma unroll
    for (int m = 0; m < 8; m++) {
        float u = k[m];
        int idx = 0; float cb = 0.0f;
        if (c32 <= u) { idx = 32; cb = c32; }
        float q2 = idx ? c48 : c16;
        if (q2 <= u) { idx += 16; cb = q2; }
        float q3 = (idx & 32) ? ((idx & 16) ? c56 : c40)
                              : ((idx & 16) ? c24 : c8);
        if (q3 <= u) { idx += 8; cb = q3; }
        float p4 = cdfs[idx + 4 + ((idx >> 3) & 4)];   // padded slot
        if (p4 <= u) { idx += 4; cb = p4; }
        float4 T = ta[(idx >> 2) + (idx >> 5)];        // (c[idx+1..idx+4])
        int o = 0;
        if (T.y <= u) { o = 2; cb = T.y; }
        float cn = o ? T.z : T.x;
        if (cn <= u) { o += 1; cb = cn; }
        float c1 = (o & 1) ? ((o & 2) ? T.w : T.y)
                           : ((o & 2) ? T.z : T.x);
        idx += o;
        float2 dp = dpair[idx + 2 * (idx >> 4)];       // (d[idx], d[idx+1])
        float den = c1 - cb;
        den = (den < 1e-5f) ? 1.0f : den;
        float t = (u - cb) / den;
        float s = fmaf(t, dp.y - dp.x, dp.x);
        s = fminf(s, dp.y);
        obf[OSL(hl * 8 + m + idx + 1)] = s;            // pos = rank + bin + 1
        if (m == 0) idx0 = idx;
        else if (idx != prev) pref[idx] = hl * 8 + m;
        prev = idx;
    }
    int pb = __shfl_up_sync(FULL, prev, 1);
    if (hl == 0) pb = -1;
    if (idx0 != pb) pref[idx0] = hl * 8;
    __syncwarp();

    // ---- suffix-min over pref[0..63] (4 per lane) ----
    int4 P = ((int4*)pref)[hl];
    int s3 = P.w;
    int s2 = min(P.z, s3);
    int s1 = min(P.y, s2);
    int s0 = min(P.x, s1);
    int S = s0;
    #pragma unroll
    for (int off = 1; off < 16; off <<= 1) {
        int t = __shfl_down_sync(FULL, S, off);
        if (hl + off < 16) S = min(S, t);
    }
    int Sn = __shfl_down_sync(FULL, S, 1);
    if (hl == 15) Sn = 128;
    int f3 = min(s3, Sn);
    int f2 = min(s2, f3);
    int f1 = min(s1, f2);
    int f0 = min(s0, f1);

    // ---- dists (register-resident): pos = j + prefix[j] ----
    obf[OSL(wi     + f0)] = dd.x;
    obf[OSL(wi + 1 + f1)] = dd.y;
    obf[OSL(wi + 2 + f2)] = dd.z;
    obf[OSL(wi + 3 + f3)] = dd.w;
    __syncwarp();

    // ---- vectorized coalesced output (both rays contiguous) ----
    float4* op4 = (float4*)(out + (size_t)(ray - half) * NOUT);
    #pragma unroll
    for (int t = 0; t < 3; t++) {
        int e0 = t * 128 + lane * 4;             // warp element 0..383
        int h  = e0 >= NOUT;
        int local = e0 - (h ? NOUT : 0);
        const float4* src = (const float4*)(out_s[wid][h] + OSL(local));
        op4[t * 32 + lane] = *src;
    }
}

extern "C" void kernel_launch(void* const* d_in, const int* in_sizes, int n_in,
                              void* d_out, int out_size) {
    const float* dists   = (const float*)d_in[0];
    const float* weights = (const float*)d_in[1];
    const float* rands   = (const float*)d_in[2];
    float* out = (float*)d_out;
    int B = in_sizes[0] / SC;
    int raysPerBlock = 2 * WPB;
    int blocks = (B + raysPerBlock - 1) / raysPerBlock;
    fine_sample_kernel<<<blocks, 32 * WPB>>>(dists, weights, rands, out, B);
}

// round 14
// speedup vs baseline: 1.0810x; 1.0810x over previous
#include <cuda_runtime.h>

// NeRF fine sampling + merge. TWO rays per warp (16 lanes x 8 elements each).
// R11 + cheap swizzle on dpair (4-way aliasing) and ta (2-way), float2-aligned.
#define SC   64
#define SF   128
#define NOUT 192
#define WPB  8
#define FULL 0xffffffffu

// per-(warp,half) blob layout (float offsets)
#define TA_OFF    0     // float4[18]: ta[g] at slot g+(g>>3)
#define DP_OFF    72    // float2[69]: dpair[i] at slot i+(i>>4)
#define CDF_OFF   216   // float[68]:  cdf[0..63] plain
#define PREF_OFF  284   // int[64]
#define BLOB_SZ   360   // mod 32 = 8 -> halves de-aliased

__device__ __forceinline__ void ce(float& x, float& y, bool asc) {
    float lo = fminf(x, y), hi = fmaxf(x, y);
    x = asc ? lo : hi;
    y = asc ? hi : lo;
}

__global__ __launch_bounds__(32 * WPB, 6)
void fine_sample_kernel(const float* __restrict__ dists,
                        const float* __restrict__ weights,
                        const float* __restrict__ rands,
                        float* __restrict__ out, int B)
{
    __shared__ __align__(16) float blob_s[WPB][2][BLOB_SZ];
    __shared__ __align__(16) float out_s[WPB][2][NOUT];

    const int wid  = threadIdx.x >> 5;
    const int lane = threadIdx.x & 31;
    const int half = lane >> 4;
    const int hl   = lane & 15;
    const int ray  = (blockIdx.x * WPB + wid) * 2 + half;

    float* blob = blob_s[wid][half];
    float4* ta    = (float4*)(blob + TA_OFF);
    float2* dpair = (float2*)(blob + DP_OFF);
    float*  cdfs  = blob + CDF_OFF;
    int*    pref  = (int*)(blob + PREF_OFF);

    // pref default: 128
    ((int4*)pref)[hl] = make_int4(128, 128, 128, 128);

    const int wi = 4 * hl;
    {
        // ---- loads ----
        const float4* dptr4 = (const float4*)(dists + (size_t)ray * SC);
        float4 dd = dptr4[hl];                               // d[4hl..4hl+3]
        const float* wptr = weights + (size_t)ray * (SC - 1);
        float w0 = wptr[wi]     + 0.01f;
        float w1 = wptr[wi + 1] + 0.01f;
        float w2 = wptr[wi + 2] + 0.01f;
        float w3 = (hl < 15) ? (wptr[wi + 3] + 0.01f) : 0.0f;

        // ---- scan (width 16, both rays in parallel) ----
        float p1 = w0, p2 = p1 + w1, p3 = p2 + w2;
        float e  = p3 + w3;
        float E = e;
        #pragma unroll
        for (int off = 1; off < 16; off <<= 1) {
            float t = __shfl_up_sync(FULL, E, off);
            if (hl >= off) E += t;
        }
        float total = __shfl_sync(FULL, E, lane | 15);
        float inv = 1.0f / total;
        float c0e = E - e;
        float4 cv = make_float4(c0e * inv, (c0e + p1) * inv,
                                (c0e + p2) * inv, (c0e + p3) * inv);
        float ctop = E * inv;                                // cdf[4hl+4]; hl=15 -> 1.0
        ((float4*)cdfs)[hl] = cv;
        ta[hl + (hl >> 3)] = make_float4(cv.y, cv.z, cv.w, ctop);

        // ---- dpair table: (d[i], d[i+1]) at swizzled slots (float2 stores) ----
        float dnext = __shfl_down_sync(FULL, dd.x, 1);
        if (hl == 15) dnext = dd.w;                          // d[64] := d[63]
        float2* dpw = dpair + wi + (hl >> 2);                // slot = wi + (wi>>4)
        dpw[0] = make_float2(dd.x, dd.y);
        dpw[1] = make_float2(dd.y, dd.z);
        dpw[2] = make_float2(dd.z, dd.w);
        dpw[3] = make_float2(dd.w, dnext);
    }

    // ---- load 8 u's (element index i = hl*8 + m) ----
    float k[8];
    {
        const float4* up4 = (const float4*)(rands + (size_t)ray * SF);
        float4 ua = up4[2 * hl], ub = up4[2 * hl + 1];
        k[0]=ua.x; k[1]=ua.y; k[2]=ua.z; k[3]=ua.w;
        k[4]=ub.x; k[5]=ub.y; k[6]=ub.z; k[7]=ub.w;
    }

    // ---- bitonic sort of 128 u's across 16 lanes x 8 regs ----
    ce(k[0], k[1], true);  ce(k[2], k[3], false);
    ce(k[4], k[5], true);  ce(k[6], k[7], false);
    ce(k[0], k[2], true);  ce(k[1], k[3], true);
    ce(k[0], k[1], true);  ce(k[2], k[3], true);
    ce(k[4], k[6], false); ce(k[5], k[7], false);
    ce(k[4], k[5], false); ce(k[6], k[7], false);
    {
        bool a = (hl & 1) == 0;
        ce(k[0], k[4], a); ce(k[1], k[5], a); ce(k[2], k[6], a); ce(k[3], k[7], a);
        ce(k[0], k[2], a); ce(k[1], k[3], a); ce(k[4], k[6], a); ce(k[5], k[7], a);
        ce(k[0], k[1], a); ce(k[2], k[3], a); ce(k[4], k[5], a); ce(k[6], k[7], a);
    }
    #pragma unroll
    for (int kk = 16; kk <= 128; kk <<= 1) {
        bool a = (hl & (kk >> 3)) == 0;
        #pragma unroll
        for (int L = kk >> 4; L >= 1; L >>= 1) {
            bool dm = (((hl & L) == 0) == a);
            #pragma unroll
            for (int m = 0; m < 8; m++) {
                float p = __shfl_xor_sync(FULL, k[m], L);
                k[m] = dm ? fminf(k[m], p) : fmaxf(k[m], p);
            }
        }
        ce(k[0], k[4], a); ce(k[1], k[5], a); ce(k[2], k[6], a); ce(k[3], k[7], a);
        ce(k[0], k[2], a); ce(k[1], k[3], a); ce(k[4], k[6], a); ce(k[5], k[7], a);
        ce(k[0], k[1], a); ce(k[2], k[3], a); ce(k[4], k[5], a); ce(k[6], k[7], a);
    }
    __syncwarp();   // tables ready

    // ---- reload probes (broadcast LDS, keeps sort live-set small) ----
    float c8  = cdfs[8],  c16 = cdfs[16], c24 = cdfs[24], c32 = cdfs[32];
    float c40 = cdfs[40], c48 = cdfs[48], c56 = cdfs[56];

    float* obf = out_s[wid][half];

    // ---- search + interp on SORTED u's; scatter; first-occurrence ----
    int prev = -1, idx0 = 0;
    #pragma unroll
    for (int m = 0; m < 8; m++) {
        float u = k[m];
        int idx = 0; float cb = 0.0f;
        if (c32 <= u) { idx = 32; cb = c32; }
        float q2 = idx ? c48 : c16;
        if (q2 <= u) { idx += 16; cb = q2; }
        float q3 = (idx & 32) ? ((idx & 16) ? c56 : c40)
                              : ((idx & 16) ? c24 : c8);
        if (q3 <= u) { idx += 8; cb = q3; }
        float p4 = cdfs[idx + 4];
        if (p4 <= u) { idx += 4; cb = p4; }
        float4 T = ta[(idx >> 2) + (idx >> 5)];        // (c[idx+1..idx+4])
        int o = 0;
        if (T.y <= u) { o = 2; cb = T.y; }
        float cn = o ? T.z : T.x;
        if (cn <= u) { o += 1; cb = cn; }
        float c1 = (o & 1) ? ((o & 2) ? T.w : T.y)
                           : ((o & 2) ? T.z : T.x);
        idx += o;
        float2 dp = dpair[idx + (idx >> 4)];           // (d[idx], d[idx+1])
        float den = c1 - cb;
        den = (den < 1e-5f) ? 1.0f : den;
        float t = (u - cb) / den;
        float s = fmaf(t, dp.y - dp.x, dp.x);
        s = fminf(s, dp.y);
        obf[hl * 8 + m + idx + 1] = s;                 // pos = rank + bin + 1
        if (m == 0) idx0 = idx;
        else if (idx != prev) pref[idx] = hl * 8 + m;
        prev = idx;
    }
    int pb = __shfl_up_sync(FULL, prev, 1);
    if (hl == 0) pb = -1;
    if (idx0 != pb) pref[idx0] = hl * 8;
    __syncwarp();

    // ---- suffix-min over pref[0..63] (4 per lane) ----
    int4 P = ((int4*)pref)[hl];
    int s3 = P.w;
    int s2 = min(P.z, s3);
    int s1 = min(P.y, s2);
    int s0 = min(P.x, s1);
    int S = s0;
    #pragma unroll
    for (int off = 1; off < 16; off <<= 1) {
        int t = __shfl_down_sync(FULL, S, off);
        if (hl + off < 16) S = min(S, t);
    }
    int Sn = __shfl_down_sync(FULL, S, 1);
    if (hl == 15) Sn = 128;
    int f3 = min(s3, Sn);
    int f2 = min(s2, f3);
    int f1 = min(s1, f2);
    int f0 = min(s0, f1);

    // ---- dists reloaded from dpair (float2 reads); pos = j + prefix[j] ----
    float2* dpw = dpair + wi + (hl >> 2);
    float2 g0 = dpw[0];                // (d0, d1)
    float2 g1 = dpw[1];                // (d1, d2)
    float2 g2 = dpw[2];                // (d2, d3)
    float2 g3 = dpw[3];                // (d3, d4)
    obf[wi     + f0] = g0.x;
    obf[wi + 1 + f1] = g1.x;
    obf[wi + 2 + f2] = g2.x;
    obf[wi + 3 + f3] = g3.x;
    __syncwarp();

    // ---- vectorized coalesced output (both rays contiguous) ----
    const float4* ob4 = (const float4*)out_s[wid][0];
    float4* op4 = (float4*)(out + (size_t)(ray - half) * NOUT);
    #pragma unroll
    for (int t = 0; t < 3; t++)
        op4[t * 32 + lane] = ob4[t * 32 + lane];
}

extern "C" void kernel_launch(void* const* d_in, const int* in_sizes, int n_in,
                              void* d_out, int out_size) {
    const float* dists   = (const float*)d_in[0];
    const float* weights = (const float*)d_in[1];
    const float* rands   = (const float*)d_in[2];
    float* out = (float*)d_out;
    int B = in_sizes[0] / SC;
    int raysPerBlock = 2 * WPB;
    int blocks = (B + raysPerBlock - 1) / raysPerBlock;
    fine_sample_kernel<<<blocks, 32 * WPB>>>(dists, weights, rands, out, B);
}